// round 1
// baseline (speedup 1.0000x reference)
#include <cuda_runtime.h>
#include <cstddef>

#define N_NODES_MAX 50000
#define IN_CH   128
#define HID_CH  256
#define OUT_CH  128
#define BN_EPS  1e-5f

// ---------------- scratch (device globals; no allocation allowed) ----------------
__device__ float g_h1[(size_t)N_NODES_MAX * HID_CH];   // x @ W1
__device__ float g_y1[(size_t)N_NODES_MAX * HID_CH];   // agg1, then combined layer-1 output
__device__ float g_h2[(size_t)N_NODES_MAX * OUT_CH];   // bn(y1) @ W2
__device__ float g_deg[N_NODES_MAX];
__device__ float g_dis[N_NODES_MAX];                   // rsqrt(deg+1)
__device__ float g_bnsum[HID_CH];
__device__ float g_bnsq[HID_CH];
__device__ float g_scale[HID_CH];                      // gamma * rsigma
__device__ float g_shift[HID_CH];                      // beta - mu * scale

// ---------------- zero pass ----------------
__global__ void k_zero(float* __restrict__ out, long total, int M, int outN) {
    long stride = (long)gridDim.x * blockDim.x;
    for (long i = (long)blockIdx.x * blockDim.x + threadIdx.x; i < total; i += stride) {
        g_y1[i] = 0.f;
        if (i < M) g_deg[i] = 0.f;
        if (i < HID_CH) { g_bnsum[i] = 0.f; g_bnsq[i] = 0.f; }
        if (i < outN) out[i] = 0.f;
    }
}

// ---------------- degree / normalization ----------------
__global__ void k_deg(const int* __restrict__ dst, int E) {
    int i = blockIdx.x * blockDim.x + threadIdx.x;
    if (i < E) atomicAdd(&g_deg[dst[i]], 1.0f);
}

__global__ void k_dis(int M) {
    int i = blockIdx.x * blockDim.x + threadIdx.x;
    if (i < M) g_dis[i] = rsqrtf(g_deg[i] + 1.0f);
}

// ---------------- tiled SGEMM: C[M,N] = op(A)[M,K] @ B[K,N] ----------------
// BN_A: apply relu(a*scale[k]+shift[k]) to A elements on load (fused BN+ReLU).
template <bool BN_A>
__global__ __launch_bounds__(256) void k_sgemm(const float* __restrict__ A,
                                               const float* __restrict__ B,
                                               float* __restrict__ C,
                                               int M, int N, int K) {
    constexpr int BM = 128, BNt = 128, BK = 8, TM = 8, TN = 8;
    __shared__ float As[BK][BM];
    __shared__ float Bs[BK][BNt];

    const int tid  = threadIdx.x;            // 256 threads
    const int trow = tid / (BNt / TN);       // 0..15
    const int tcol = tid % (BNt / TN);       // 0..15
    const int rowBase = blockIdx.y * BM;
    const int colBase = blockIdx.x * BNt;

    float acc[TM][TN];
#pragma unroll
    for (int i = 0; i < TM; i++)
#pragma unroll
        for (int j = 0; j < TN; j++) acc[i][j] = 0.f;

    for (int k0 = 0; k0 < K; k0 += BK) {
        // load A tile (BM x BK), store transposed As[k][m]
#pragma unroll
        for (int i = 0; i < 4; i++) {
            int idx = tid + i * 256;         // 0..1023
            int r   = idx >> 3;              // 0..127
            int kk  = idx & 7;
            int grow = rowBase + r;
            float v = 0.f;
            if (grow < M) {
                v = A[(size_t)grow * K + (k0 + kk)];
                if (BN_A) v = fmaxf(v * g_scale[k0 + kk] + g_shift[k0 + kk], 0.f);
            }
            As[kk][r] = v;
        }
        // load B tile (BK x BNt)
#pragma unroll
        for (int i = 0; i < 4; i++) {
            int idx = tid + i * 256;
            int r   = idx >> 7;              // 0..7
            int cc  = idx & 127;
            Bs[r][cc] = B[(size_t)(k0 + r) * N + colBase + cc];
        }
        __syncthreads();

#pragma unroll
        for (int kk = 0; kk < BK; kk++) {
            float ra[TM], rb[TN];
#pragma unroll
            for (int i = 0; i < TM; i++) ra[i] = As[kk][trow * TM + i];
#pragma unroll
            for (int j = 0; j < TN; j++) rb[j] = Bs[kk][tcol * TN + j];
#pragma unroll
            for (int i = 0; i < TM; i++)
#pragma unroll
                for (int j = 0; j < TN; j++) acc[i][j] = fmaf(ra[i], rb[j], acc[i][j]);
        }
        __syncthreads();
    }

#pragma unroll
    for (int i = 0; i < TM; i++) {
        int grow = rowBase + trow * TM + i;
        if (grow < M) {
            float* crow = C + (size_t)grow * N + colBase + tcol * TN;
#pragma unroll
            for (int j = 0; j < TN; j++) crow[j] = acc[i][j];
        }
    }
}

// ---------------- edge scatter: agg[dst] += h[src] * (dis[src]*dis[dst]) ----------------
// One warp per edge; float4 vector atomics (sm_90+).
__global__ __launch_bounds__(256) void k_scatter(const int* __restrict__ src,
                                                 const int* __restrict__ dst,
                                                 const float* __restrict__ h,
                                                 float* __restrict__ agg,
                                                 int E, int C) {
    int gt   = blockIdx.x * blockDim.x + threadIdx.x;
    int edge = gt >> 5;
    int lane = gt & 31;
    if (edge >= E) return;
    int s = src[edge];        // warp-uniform: single broadcast transaction
    int d = dst[edge];
    float norm = g_dis[s] * g_dis[d];
    const float4* hr = reinterpret_cast<const float4*>(h + (size_t)s * C);
    float4*       ar = reinterpret_cast<float4*>(agg + (size_t)d * C);
    int nvec = C >> 2;        // 64 (HID) or 32 (OUT)
#pragma unroll 2
    for (int c = lane; c < nvec; c += 32) {
        float4 v = hr[c];
        float4 w = make_float4(v.x * norm, v.y * norm, v.z * norm, v.w * norm);
        atomicAdd(&ar[c], w);
    }
}

// ---------------- layer-1 combine + BN stats ----------------
// y = agg1 + h1 * dis^2 + b1  (in place into g_y1) ; accumulate per-channel sum/sumsq
__global__ __launch_bounds__(HID_CH) void k_combine_bn(const float* __restrict__ b1, int M) {
    int c    = threadIdx.x;                  // channel 0..255
    int row0 = blockIdx.x * 64;
    int rowE = min(row0 + 64, M);
    float bc = b1[c];
    float sum = 0.f, sq = 0.f;
    for (int r = row0; r < rowE; r++) {
        float dis  = g_dis[r];
        float self = dis * dis;
        size_t idx = (size_t)r * HID_CH + c;
        float y = g_y1[idx] + g_h1[idx] * self + bc;
        g_y1[idx] = y;
        sum += y;
        sq  += y * y;
    }
    atomicAdd(&g_bnsum[c], sum);
    atomicAdd(&g_bnsq[c], sq);
}

__global__ void k_bn_finalize(const float* __restrict__ gamma,
                              const float* __restrict__ beta, int M) {
    int c = threadIdx.x;
    if (c >= HID_CH) return;
    float inv = 1.0f / (float)M;
    float mu  = g_bnsum[c] * inv;
    float var = g_bnsq[c] * inv - mu * mu;
    float rs  = rsqrtf(var + BN_EPS);
    float sc  = gamma[c] * rs;
    g_scale[c] = sc;
    g_shift[c] = beta[c] - mu * sc;
}

// ---------------- layer-2 epilogue: out += h2 * dis^2 + b2 ----------------
__global__ void k_final(float* __restrict__ out, const float* __restrict__ b2, int M) {
    long total  = (long)M * OUT_CH;
    long stride = (long)gridDim.x * blockDim.x;
    for (long i = (long)blockIdx.x * blockDim.x + threadIdx.x; i < total; i += stride) {
        int r = (int)(i >> 7);               // /128
        int c = (int)(i & 127);
        float dis = g_dis[r];
        out[i] += g_h2[i] * dis * dis + b2[c];
    }
}

// ---------------- launch ----------------
extern "C" void kernel_launch(void* const* d_in, const int* in_sizes, int n_in,
                              void* d_out, int out_size) {
    const float* x      = (const float*)d_in[0];
    const int*   ei     = (const int*)  d_in[1];
    const float* W1     = (const float*)d_in[2];
    const float* b1     = (const float*)d_in[3];
    const float* gamma1 = (const float*)d_in[4];
    const float* beta1  = (const float*)d_in[5];
    const float* W2     = (const float*)d_in[6];
    const float* b2     = (const float*)d_in[7];
    float* out = (float*)d_out;

    const int M = in_sizes[0] / IN_CH;       // 50000
    const int E = in_sizes[1] / 2;           // 800000
    const int* src = ei;
    const int* dst = ei + E;

    float *ph1, *py1, *ph2;
    cudaGetSymbolAddress((void**)&ph1, g_h1);
    cudaGetSymbolAddress((void**)&py1, g_y1);
    cudaGetSymbolAddress((void**)&ph2, g_h2);

    // 1. zero scratch (agg1, deg, bn accumulators, out)
    long ztotal = (long)M * HID_CH;
    k_zero<<<4096, 256>>>(out, ztotal, M, out_size);

    // 2. degrees + normalization factors
    k_deg<<<(E + 255) / 256, 256>>>(dst, E);
    k_dis<<<(M + 255) / 256, 256>>>(M);

    // 3. h1 = x @ W1
    {
        dim3 grid((HID_CH + 127) / 128, (M + 127) / 128);
        k_sgemm<false><<<grid, 256>>>(x, W1, ph1, M, HID_CH, IN_CH);
    }

    // 4. agg1[dst] += h1[src] * norm
    {
        long threads = (long)E * 32;
        int blocks = (int)((threads + 255) / 256);
        k_scatter<<<blocks, 256>>>(src, dst, ph1, py1, E, HID_CH);
    }

    // 5. y1 = agg1 + h1*dis^2 + b1 ; BN stats
    k_combine_bn<<<(M + 63) / 64, HID_CH>>>(b1, M);
    k_bn_finalize<<<1, HID_CH>>>(gamma1, beta1, M);

    // 6. h2 = relu(bn(y1)) @ W2  (BN+ReLU fused into A load)
    {
        dim3 grid((OUT_CH + 127) / 128, (M + 127) / 128);
        k_sgemm<true><<<grid, 256>>>(py1, W2, ph2, M, OUT_CH, HID_CH);
    }

    // 7. out[dst] += h2[src] * norm   (out already zeroed)
    {
        long threads = (long)E * 32;
        int blocks = (int)((threads + 255) / 256);
        k_scatter<<<blocks, 256>>>(src, dst, ph2, out, E, OUT_CH);
    }

    // 8. out += h2*dis^2 + b2
    k_final<<<8192, 256>>>(out, b2, M);
}

// round 4
// speedup vs baseline: 2.6516x; 2.6516x over previous
#include <cuda_runtime.h>
#include <cstddef>

#define N_NODES_MAX 50000
#define E_MAX       800000
#define IN_CH   128
#define HID_CH  256
#define OUT_CH  128
#define BN_EPS  1e-5f

// ---------------- scratch (device globals) ----------------
__device__ float g_h1[(size_t)N_NODES_MAX * HID_CH];   // x @ W1
__device__ float g_y1[(size_t)N_NODES_MAX * HID_CH];   // layer-1 output (post combine)
__device__ float g_h2[(size_t)N_NODES_MAX * OUT_CH];   // bn-relu(y1) @ W2
__device__ int   g_degi[N_NODES_MAX];                  // in-degree histogram
__device__ int   g_cur[N_NODES_MAX];                   // fill cursors
__device__ int   g_off[N_NODES_MAX];                   // CSR row offsets (by dst)
__device__ int   g_esrc[E_MAX];                        // CSR: src id per slot
__device__ int   g_bsum[256];                          // scan partials
__device__ int   g_bscan[256];
__device__ float g_dis[N_NODES_MAX];                   // rsqrt(deg+1)
__device__ float g_bnsum[HID_CH];
__device__ float g_bnsq[HID_CH];
__device__ float g_scale[HID_CH];                      // gamma * rsigma
__device__ float g_shift[HID_CH];                      // beta - mu * scale

__device__ __forceinline__ void fma4(float4& a, const float4 v, const float s) {
    a.x = fmaf(v.x, s, a.x);
    a.y = fmaf(v.y, s, a.y);
    a.z = fmaf(v.z, s, a.z);
    a.w = fmaf(v.w, s, a.w);
}

// ---------------- init ----------------
__global__ void k_init(int M) {
    int stride = gridDim.x * blockDim.x;
    for (int i = blockIdx.x * blockDim.x + threadIdx.x; i < M; i += stride) {
        g_degi[i] = 0;
        g_cur[i]  = 0;
        if (i < HID_CH) { g_bnsum[i] = 0.f; g_bnsq[i] = 0.f; }
    }
}

// ---------------- degree histogram ----------------
__global__ void k_deg(const int* __restrict__ dst, int E) {
    int i = blockIdx.x * blockDim.x + threadIdx.x;
    if (i < E) atomicAdd(&g_degi[dst[i]], 1);
}

__global__ void k_dis(int M) {
    int i = blockIdx.x * blockDim.x + threadIdx.x;
    if (i < M) g_dis[i] = rsqrtf((float)g_degi[i] + 1.0f);
}

// ---------------- exclusive scan over degrees (3-pass, M <= 65536) ----------------
__global__ void k_scan1(int M) {
    __shared__ int s[256];
    int tid = threadIdx.x;
    int i = blockIdx.x * 256 + tid;
    int v = (i < M) ? g_degi[i] : 0;
    s[tid] = v;
    __syncthreads();
#pragma unroll
    for (int off = 1; off < 256; off <<= 1) {
        int t = (tid >= off) ? s[tid - off] : 0;
        __syncthreads();
        s[tid] += t;
        __syncthreads();
    }
    if (i < M) g_off[i] = s[tid] - v;
    if (tid == 255) g_bsum[blockIdx.x] = s[255];
}

__global__ void k_scan2(int NB) {
    __shared__ int s[256];
    int tid = threadIdx.x;
    int v = (tid < NB) ? g_bsum[tid] : 0;
    s[tid] = v;
    __syncthreads();
#pragma unroll
    for (int off = 1; off < 256; off <<= 1) {
        int t = (tid >= off) ? s[tid - off] : 0;
        __syncthreads();
        s[tid] += t;
        __syncthreads();
    }
    g_bscan[tid] = s[tid] - v;   // exclusive
}

__global__ void k_scan3(int M) {
    int i = blockIdx.x * blockDim.x + threadIdx.x;
    if (i < M) g_off[i] += g_bscan[i >> 8];
}

// ---------------- CSR fill ----------------
__global__ void k_fill(const int* __restrict__ src, const int* __restrict__ dst, int E) {
    int i = blockIdx.x * blockDim.x + threadIdx.x;
    if (i < E) {
        int d = dst[i];
        int pos = g_off[d] + atomicAdd(&g_cur[d], 1);
        g_esrc[pos] = src[i];
    }
}

// ---------------- persistent double-buffered SGEMM ----------------
// C[M,N_] = op(A)[M,K_] @ B[K_,N_].  BN_A fuses relu(a*scale+shift) on A load.
template <bool BN_A, int BM_, int TM_, int N_, int K_>
__global__ __launch_bounds__(256, 2) void k_sgemm(const float* __restrict__ A,
                                                  const float* __restrict__ B,
                                                  float* __restrict__ C, int M) {
    constexpr int BK = 16, BNt = 128, TN = 8;
    constexpr int APAD = BM_ + 4;
    constexpr int AF4 = BM_ / 64;     // float4 per thread per A stage
    constexpr int KT = K_ / BK;
    __shared__ float As[2][BK][APAD];
    __shared__ float Bs[2][BK][BNt];

    const int tid  = threadIdx.x;
    const int trow = tid >> 4;        // 0..15
    const int tcol = tid & 15;        // 0..15
    const int ntm = (M + BM_ - 1) / BM_;
    const int ntn = N_ / BNt;
    const int ntiles = ntm * ntn;

    for (int tile = blockIdx.x; tile < ntiles; tile += gridDim.x) {
        const int rowBase = (tile / ntn) * BM_;
        const int colBase = (tile % ntn) * BNt;

        float acc[TM_][TN];
#pragma unroll
        for (int i = 0; i < TM_; i++)
#pragma unroll
            for (int j = 0; j < TN; j++) acc[i][j] = 0.f;

        float4 pa[AF4], pb[2];

        // ---- stage-0 load ----
#pragma unroll
        for (int it = 0; it < AF4; it++) {
            int f = tid + it * 256;
            int r = f >> 2, kq = f & 3;
            int grow = rowBase + r;
            float4 v = make_float4(0.f, 0.f, 0.f, 0.f);
            if (grow < M) {
                v = *(const float4*)(A + (size_t)grow * K_ + kq * 4);
                if (BN_A) {
                    float4 sc = *(const float4*)(g_scale + kq * 4);
                    float4 sh = *(const float4*)(g_shift + kq * 4);
                    v.x = fmaxf(fmaf(v.x, sc.x, sh.x), 0.f);
                    v.y = fmaxf(fmaf(v.y, sc.y, sh.y), 0.f);
                    v.z = fmaxf(fmaf(v.z, sc.z, sh.z), 0.f);
                    v.w = fmaxf(fmaf(v.w, sc.w, sh.w), 0.f);
                }
            }
            pa[it] = v;
        }
#pragma unroll
        for (int it = 0; it < 2; it++) {
            int f = tid + it * 256;
            int r = f >> 5, c = f & 31;
            pb[it] = *(const float4*)(B + (size_t)r * N_ + colBase + c * 4);
        }
#pragma unroll
        for (int it = 0; it < AF4; it++) {
            int f = tid + it * 256;
            int r = f >> 2, kq = f & 3;
            As[0][kq * 4 + 0][r] = pa[it].x;
            As[0][kq * 4 + 1][r] = pa[it].y;
            As[0][kq * 4 + 2][r] = pa[it].z;
            As[0][kq * 4 + 3][r] = pa[it].w;
        }
#pragma unroll
        for (int it = 0; it < 2; it++) {
            int f = tid + it * 256;
            int r = f >> 5, c = f & 31;
            *(float4*)&Bs[0][r][c * 4] = pb[it];
        }
        __syncthreads();

        int buf = 0;
        for (int t = 0; t < KT; t++) {
            if (t + 1 < KT) {
                int k0 = (t + 1) * BK;
#pragma unroll
                for (int it = 0; it < AF4; it++) {
                    int f = tid + it * 256;
                    int r = f >> 2, kq = f & 3;
                    int grow = rowBase + r;
                    float4 v = make_float4(0.f, 0.f, 0.f, 0.f);
                    if (grow < M) {
                        v = *(const float4*)(A + (size_t)grow * K_ + k0 + kq * 4);
                        if (BN_A) {
                            float4 sc = *(const float4*)(g_scale + k0 + kq * 4);
                            float4 sh = *(const float4*)(g_shift + k0 + kq * 4);
                            v.x = fmaxf(fmaf(v.x, sc.x, sh.x), 0.f);
                            v.y = fmaxf(fmaf(v.y, sc.y, sh.y), 0.f);
                            v.z = fmaxf(fmaf(v.z, sc.z, sh.z), 0.f);
                            v.w = fmaxf(fmaf(v.w, sc.w, sh.w), 0.f);
                        }
                    }
                    pa[it] = v;
                }
#pragma unroll
                for (int it = 0; it < 2; it++) {
                    int f = tid + it * 256;
                    int r = f >> 5, c = f & 31;
                    pb[it] = *(const float4*)(B + (size_t)(k0 + r) * N_ + colBase + c * 4);
                }
            }

            // ---- compute on buf ----
#pragma unroll
            for (int kk = 0; kk < BK; kk++) {
                float ra[TM_], rb[TN];
#pragma unroll
                for (int i = 0; i < TM_ / 4; i++)
                    *(float4*)&ra[i * 4] = *(const float4*)&As[buf][kk][trow * TM_ + i * 4];
#pragma unroll
                for (int j = 0; j < 2; j++)
                    *(float4*)&rb[j * 4] = *(const float4*)&Bs[buf][kk][tcol * 8 + j * 4];
#pragma unroll
                for (int i = 0; i < TM_; i++)
#pragma unroll
                    for (int j = 0; j < TN; j++)
                        acc[i][j] = fmaf(ra[i], rb[j], acc[i][j]);
            }

            if (t + 1 < KT) {
                int nxt = buf ^ 1;
#pragma unroll
                for (int it = 0; it < AF4; it++) {
                    int f = tid + it * 256;
                    int r = f >> 2, kq = f & 3;
                    As[nxt][kq * 4 + 0][r] = pa[it].x;
                    As[nxt][kq * 4 + 1][r] = pa[it].y;
                    As[nxt][kq * 4 + 2][r] = pa[it].z;
                    As[nxt][kq * 4 + 3][r] = pa[it].w;
                }
#pragma unroll
                for (int it = 0; it < 2; it++) {
                    int f = tid + it * 256;
                    int r = f >> 5, c = f & 31;
                    *(float4*)&Bs[nxt][r][c * 4] = pb[it];
                }
            }
            __syncthreads();
            buf ^= 1;
        }

        // ---- epilogue ----
#pragma unroll
        for (int i = 0; i < TM_; i++) {
            int grow = rowBase + trow * TM_ + i;
            if (grow < M) {
                float* crow = C + (size_t)grow * N_ + colBase + tcol * 8;
                *(float4*)(crow)     = make_float4(acc[i][0], acc[i][1], acc[i][2], acc[i][3]);
                *(float4*)(crow + 4) = make_float4(acc[i][4], acc[i][5], acc[i][6], acc[i][7]);
            }
        }
    }
}

// ---------------- layer-1 gather: y1[d] = sum_in h1[s]*norm + h1[d]*dis^2 + b1; BN stats ----------------
__global__ __launch_bounds__(256) void k_gather_bn(const float* __restrict__ b1, int M, int E) {
    __shared__ float s_sum[HID_CH], s_sq[HID_CH];
    const int tid = threadIdx.x, lane = tid & 31, wid = tid >> 5;
    s_sum[tid] = 0.f; s_sq[tid] = 0.f;
    __syncthreads();

    const float4* b4 = (const float4*)b1;
    const float4 bb0 = b4[lane], bb1 = b4[lane + 32];
    float ls[8] = {0,0,0,0,0,0,0,0}, lq[8] = {0,0,0,0,0,0,0,0};

    for (int d = blockIdx.x * 8 + wid; d < M; d += gridDim.x * 8) {
        float disd = g_dis[d];
        int beg = g_off[d];
        int end = (d == M - 1) ? E : g_off[d + 1];
        float4 a0 = make_float4(0.f,0.f,0.f,0.f), a1 = make_float4(0.f,0.f,0.f,0.f);

        int j = beg;
        for (; j + 2 <= end; j += 2) {
            int s0 = g_esrc[j], s1 = g_esrc[j + 1];
            float w0 = disd * g_dis[s0];
            float w1 = disd * g_dis[s1];
            const float4* r0 = (const float4*)(g_h1 + (size_t)s0 * HID_CH);
            const float4* r1 = (const float4*)(g_h1 + (size_t)s1 * HID_CH);
            float4 v00 = r0[lane], v01 = r0[lane + 32];
            float4 v10 = r1[lane], v11 = r1[lane + 32];
            fma4(a0, v00, w0); fma4(a1, v01, w0);
            fma4(a0, v10, w1); fma4(a1, v11, w1);
        }
        if (j < end) {
            int s0 = g_esrc[j];
            float w0 = disd * g_dis[s0];
            const float4* r0 = (const float4*)(g_h1 + (size_t)s0 * HID_CH);
            float4 v00 = r0[lane], v01 = r0[lane + 32];
            fma4(a0, v00, w0); fma4(a1, v01, w0);
        }
        // self-loop + bias
        float self = disd * disd;
        const float4* hd = (const float4*)(g_h1 + (size_t)d * HID_CH);
        float4 sv0 = hd[lane], sv1 = hd[lane + 32];
        fma4(a0, sv0, self); fma4(a1, sv1, self);
        a0.x += bb0.x; a0.y += bb0.y; a0.z += bb0.z; a0.w += bb0.w;
        a1.x += bb1.x; a1.y += bb1.y; a1.z += bb1.z; a1.w += bb1.w;

        float4* yr = (float4*)(g_y1 + (size_t)d * HID_CH);
        yr[lane] = a0; yr[lane + 32] = a1;

        ls[0] += a0.x; lq[0] += a0.x * a0.x;
        ls[1] += a0.y; lq[1] += a0.y * a0.y;
        ls[2] += a0.z; lq[2] += a0.z * a0.z;
        ls[3] += a0.w; lq[3] += a0.w * a0.w;
        ls[4] += a1.x; lq[4] += a1.x * a1.x;
        ls[5] += a1.y; lq[5] += a1.y * a1.y;
        ls[6] += a1.z; lq[6] += a1.z * a1.z;
        ls[7] += a1.w; lq[7] += a1.w * a1.w;
    }

#pragma unroll
    for (int j = 0; j < 4; j++) {
        atomicAdd(&s_sum[4 * lane + j], ls[j]);
        atomicAdd(&s_sq [4 * lane + j], lq[j]);
        atomicAdd(&s_sum[128 + 4 * lane + j], ls[4 + j]);
        atomicAdd(&s_sq [128 + 4 * lane + j], lq[4 + j]);
    }
    __syncthreads();
    atomicAdd(&g_bnsum[tid], s_sum[tid]);
    atomicAdd(&g_bnsq[tid],  s_sq[tid]);
}

__global__ void k_bn_finalize(const float* __restrict__ gamma,
                              const float* __restrict__ beta, int M) {
    int c = threadIdx.x;
    if (c >= HID_CH) return;
    float inv = 1.0f / (float)M;
    float mu  = g_bnsum[c] * inv;
    float var = g_bnsq[c] * inv - mu * mu;
    float rs  = rsqrtf(var + BN_EPS);
    float sc  = gamma[c] * rs;
    g_scale[c] = sc;
    g_shift[c] = beta[c] - mu * sc;
}

// ---------------- layer-2 gather: out[d] = sum_in h2[s]*norm + h2[d]*dis^2 + b2 ----------------
__global__ __launch_bounds__(256) void k_gather_out(float* __restrict__ out,
                                                    const float* __restrict__ b2, int M, int E) {
    const int tid = threadIdx.x, lane = tid & 31, wid = tid >> 5;
    const float4 bb = ((const float4*)b2)[lane];

    for (int d = blockIdx.x * 8 + wid; d < M; d += gridDim.x * 8) {
        float disd = g_dis[d];
        int beg = g_off[d];
        int end = (d == M - 1) ? E : g_off[d + 1];
        float4 a = make_float4(0.f,0.f,0.f,0.f);

        int j = beg;
        for (; j + 2 <= end; j += 2) {
            int s0 = g_esrc[j], s1 = g_esrc[j + 1];
            float w0 = disd * g_dis[s0];
            float w1 = disd * g_dis[s1];
            float4 v0 = ((const float4*)(g_h2 + (size_t)s0 * OUT_CH))[lane];
            float4 v1 = ((const float4*)(g_h2 + (size_t)s1 * OUT_CH))[lane];
            fma4(a, v0, w0);
            fma4(a, v1, w1);
        }
        if (j < end) {
            int s0 = g_esrc[j];
            float w0 = disd * g_dis[s0];
            float4 v0 = ((const float4*)(g_h2 + (size_t)s0 * OUT_CH))[lane];
            fma4(a, v0, w0);
        }
        float self = disd * disd;
        float4 sv = ((const float4*)(g_h2 + (size_t)d * OUT_CH))[lane];
        fma4(a, sv, self);
        a.x += bb.x; a.y += bb.y; a.z += bb.z; a.w += bb.w;
        ((float4*)(out + (size_t)d * OUT_CH))[lane] = a;
    }
}

// ---------------- launch ----------------
extern "C" void kernel_launch(void* const* d_in, const int* in_sizes, int n_in,
                              void* d_out, int out_size) {
    const float* x      = (const float*)d_in[0];
    const int*   ei     = (const int*)  d_in[1];
    const float* W1     = (const float*)d_in[2];
    const float* b1     = (const float*)d_in[3];
    const float* gamma1 = (const float*)d_in[4];
    const float* beta1  = (const float*)d_in[5];
    const float* W2     = (const float*)d_in[6];
    const float* b2     = (const float*)d_in[7];
    float* out = (float*)d_out;

    const int M = in_sizes[0] / IN_CH;    // 50000
    const int E = in_sizes[1] / 2;        // 800000
    const int* src = ei;
    const int* dst = ei + E;

    float *ph1, *py1, *ph2;
    cudaGetSymbolAddress((void**)&ph1, g_h1);
    cudaGetSymbolAddress((void**)&py1, g_y1);
    cudaGetSymbolAddress((void**)&ph2, g_h2);

    const int NB = (M + 255) / 256;       // scan blocks (<=256)

    // CSR build + normalization
    k_init<<<256, 256>>>(M);
    k_deg<<<(E + 255) / 256, 256>>>(dst, E);
    k_dis<<<(M + 255) / 256, 256>>>(M);
    k_scan1<<<NB, 256>>>(M);
    k_scan2<<<1, 256>>>(NB);
    k_scan3<<<(M + 255) / 256, 256>>>(M);
    k_fill<<<(E + 255) / 256, 256>>>(src, dst, E);

    // layer 1
    k_sgemm<false, 128, 8, HID_CH, IN_CH><<<296, 256>>>(x, W1, ph1, M);
    k_gather_bn<<<592, 256>>>(b1, M, E);
    k_bn_finalize<<<1, HID_CH>>>(gamma1, beta1, M);

    // layer 2 (BN+ReLU fused into A load)
    k_sgemm<true, 64, 4, OUT_CH, HID_CH><<<296, 256>>>(py1, W2, ph2, M);
    k_gather_out<<<592, 256>>>(out, b2, M, E);
}

// round 6
// speedup vs baseline: 4.1767x; 1.5752x over previous
#include <cuda_runtime.h>
#include <cuda_bf16.h>
#include <cstddef>
#include <cstdint>

#define N_NODES_MAX 50000
#define E_MAX       800000
#define IN_CH   128
#define HID_CH  256
#define OUT_CH  128
#define BN_EPS  1e-5f
#define SA      144      // smem row stride (bytes) for 64-bf16 rows + 16B pad

// ---------------- scratch (device globals) ----------------
__device__ float g_h1[(size_t)N_NODES_MAX * HID_CH];   // x @ W1
__device__ float g_y1[(size_t)N_NODES_MAX * HID_CH];   // layer-1 output (post combine)
__device__ float g_h2[(size_t)N_NODES_MAX * OUT_CH];   // bn-relu(y1) @ W2
__device__ int   g_degi[N_NODES_MAX];
__device__ int   g_cur[N_NODES_MAX];
__device__ int   g_off[N_NODES_MAX];
__device__ int   g_esrc[E_MAX];
__device__ int   g_bsum[256];
__device__ int   g_bscan[256];
__device__ float g_dis[N_NODES_MAX];
__device__ float g_bnsum[HID_CH];
__device__ float g_bnsq[HID_CH];
__device__ float g_scale[HID_CH];
__device__ float g_shift[HID_CH];
// W transposed + split to bf16 (K-major rows: [N][K])
__device__ __align__(16) __nv_bfloat16 g_wt1hi[HID_CH * IN_CH];   // [256,128]
__device__ __align__(16) __nv_bfloat16 g_wt1lo[HID_CH * IN_CH];
__device__ __align__(16) __nv_bfloat16 g_wt2hi[OUT_CH * HID_CH];  // [128,256]
__device__ __align__(16) __nv_bfloat16 g_wt2lo[OUT_CH * HID_CH];

__device__ __forceinline__ void fma4(float4& a, const float4 v, const float s) {
    a.x = fmaf(v.x, s, a.x);
    a.y = fmaf(v.y, s, a.y);
    a.z = fmaf(v.z, s, a.z);
    a.w = fmaf(v.w, s, a.w);
}

__device__ __forceinline__ uint32_t smem_u32(const void* p) {
    uint32_t a;
    asm("{ .reg .u64 t; cvta.to.shared.u64 t, %1; cvt.u32.u64 %0, t; }" : "=r"(a) : "l"(p));
    return a;
}

#define LDSM_X4(r, addr) \
    asm volatile("ldmatrix.sync.aligned.m8n8.x4.shared.b16 {%0,%1,%2,%3}, [%4];" \
                 : "=r"((r)[0]), "=r"((r)[1]), "=r"((r)[2]), "=r"((r)[3]) : "r"(addr))

__device__ __forceinline__ void mma16816(float* c, const uint32_t* a, uint32_t b0, uint32_t b1) {
    asm volatile(
        "mma.sync.aligned.m16n8k16.row.col.f32.bf16.bf16.f32 "
        "{%0,%1,%2,%3}, {%4,%5,%6,%7}, {%8,%9}, {%0,%1,%2,%3};"
        : "+f"(c[0]), "+f"(c[1]), "+f"(c[2]), "+f"(c[3])
        : "r"(a[0]), "r"(a[1]), "r"(a[2]), "r"(a[3]), "r"(b0), "r"(b1));
}

// ---------------- init ----------------
__global__ void k_init(int M) {
    int stride = gridDim.x * blockDim.x;
    for (int i = blockIdx.x * blockDim.x + threadIdx.x; i < M; i += stride) {
        g_degi[i] = 0;
        g_cur[i]  = 0;
        if (i < HID_CH) { g_bnsum[i] = 0.f; g_bnsq[i] = 0.f; }
    }
}

// ---------------- W transpose + hi/lo split ----------------
__global__ void k_prep_w(const float* __restrict__ W1, const float* __restrict__ W2) {
    int i = blockIdx.x * blockDim.x + threadIdx.x;
    if (i < IN_CH * HID_CH) {                 // W1 [128,256] -> WT1 [256,128]
        int k = i / HID_CH, n = i % HID_CH;
        float v = W1[i];
        __nv_bfloat16 h = __float2bfloat16(v);
        g_wt1hi[n * IN_CH + k] = h;
        g_wt1lo[n * IN_CH + k] = __float2bfloat16(v - __bfloat162float(h));
    } else if (i < 2 * IN_CH * HID_CH) {      // W2 [256,128] -> WT2 [128,256]
        int j = i - IN_CH * HID_CH;
        int k = j / OUT_CH, n = j % OUT_CH;
        float v = W2[j];
        __nv_bfloat16 h = __float2bfloat16(v);
        g_wt2hi[n * HID_CH + k] = h;
        g_wt2lo[n * HID_CH + k] = __float2bfloat16(v - __bfloat162float(h));
    }
}

// ---------------- degree histogram ----------------
__global__ void k_deg(const int* __restrict__ dst, int E) {
    int i = blockIdx.x * blockDim.x + threadIdx.x;
    if (i < E) atomicAdd(&g_degi[dst[i]], 1);
}

__global__ void k_dis(int M) {
    int i = blockIdx.x * blockDim.x + threadIdx.x;
    if (i < M) g_dis[i] = rsqrtf((float)g_degi[i] + 1.0f);
}

// ---------------- exclusive scan over degrees ----------------
__global__ void k_scan1(int M) {
    __shared__ int s[256];
    int tid = threadIdx.x;
    int i = blockIdx.x * 256 + tid;
    int v = (i < M) ? g_degi[i] : 0;
    s[tid] = v;
    __syncthreads();
#pragma unroll
    for (int off = 1; off < 256; off <<= 1) {
        int t = (tid >= off) ? s[tid - off] : 0;
        __syncthreads();
        s[tid] += t;
        __syncthreads();
    }
    if (i < M) g_off[i] = s[tid] - v;
    if (tid == 255) g_bsum[blockIdx.x] = s[255];
}

__global__ void k_scan2(int NB) {
    __shared__ int s[256];
    int tid = threadIdx.x;
    int v = (tid < NB) ? g_bsum[tid] : 0;
    s[tid] = v;
    __syncthreads();
#pragma unroll
    for (int off = 1; off < 256; off <<= 1) {
        int t = (tid >= off) ? s[tid - off] : 0;
        __syncthreads();
        s[tid] += t;
        __syncthreads();
    }
    g_bscan[tid] = s[tid] - v;
}

__global__ void k_scan3(int M) {
    int i = blockIdx.x * blockDim.x + threadIdx.x;
    if (i < M) g_off[i] += g_bscan[i >> 8];
}

__global__ void k_fill(const int* __restrict__ src, const int* __restrict__ dst, int E) {
    int i = blockIdx.x * blockDim.x + threadIdx.x;
    if (i < E) {
        int d = dst[i];
        int pos = g_off[d] + atomicAdd(&g_cur[d], 1);
        g_esrc[pos] = src[i];
    }
}

// ---------------- mma.sync bf16-split GEMM ----------------
// C[M,NTOT] = op(A)[M,KTOT] @ W[KTOT,NTOT]; W pre-transposed+split: Bhi/Blo [NTOT][KTOT] bf16.
// BN_A fuses relu(a*scale+shift) into the A convert.
// Block tile BM x 128 (8 warps), K chunked by 64. 3 split products in fp32 accumulators.
template <bool BN_A, int KTOT, int NTOT, int BM>
__global__ __launch_bounds__(256, 2)
void k_mma_gemm(const float* __restrict__ A,
                const __nv_bfloat16* __restrict__ Bhi,
                const __nv_bfloat16* __restrict__ Blo,
                float* __restrict__ C, int M) {
    constexpr int KC = 64;
    constexpr int NCH = KTOT / KC;
    constexpr int WARPS_M = BM / 32;          // 4 (BM=128) or 2 (BM=64)
    constexpr int WARPS_N = 8 / WARPS_M;      // 2 or 4
    constexpr int WN = 128 / WARPS_N;         // warp N extent: 64 or 32
    constexpr int NT16 = WN / 16;             // 4 or 2
    constexpr int N8 = WN / 8;                // 8 or 4
    constexpr int AITER = BM * 16 / 256;      // float4 loads per thread per chunk

    extern __shared__ char sm[];
    char* Ah = sm;
    char* Al = Ah + BM * SA;
    char* Bh = Al + BM * SA;
    char* Bl = Bh + 128 * SA;

    const int tid  = threadIdx.x;
    const int lane = tid & 31;
    const int wid  = tid >> 5;
    const int warpM = wid % WARPS_M;
    const int warpN = wid / WARPS_M;
    const int rowBase = blockIdx.y * BM;
    const int colBase = blockIdx.x * 128;

    float acc[2][N8][4];
#pragma unroll
    for (int i = 0; i < 2; i++)
#pragma unroll
        for (int j = 0; j < N8; j++)
#pragma unroll
            for (int q = 0; q < 4; q++) acc[i][j][q] = 0.f;

    const uint32_t sAh = smem_u32(Ah), sAl = smem_u32(Al);
    const uint32_t sBh = smem_u32(Bh), sBl = smem_u32(Bl);

    for (int ck = 0; ck < NCH; ck++) {
        // ---- A: BM rows x 64 k fp32 -> hi/lo bf16 in smem ----
#pragma unroll
        for (int i = 0; i < AITER; i++) {
            int f = tid + i * 256;
            int r = f >> 4;                   // row 0..BM-1
            int kq = f & 15;                  // float4 within 64-k row
            int grow = rowBase + r;
            float4 v = make_float4(0.f, 0.f, 0.f, 0.f);
            if (grow < M) {
                v = *(const float4*)(A + (size_t)grow * KTOT + ck * KC + kq * 4);
                if (BN_A) {
                    const float4 sc = *(const float4*)(g_scale + ck * KC + kq * 4);
                    const float4 sh = *(const float4*)(g_shift + ck * KC + kq * 4);
                    v.x = fmaxf(fmaf(v.x, sc.x, sh.x), 0.f);
                    v.y = fmaxf(fmaf(v.y, sc.y, sh.y), 0.f);
                    v.z = fmaxf(fmaf(v.z, sc.z, sh.z), 0.f);
                    v.w = fmaxf(fmaf(v.w, sc.w, sh.w), 0.f);
                }
            }
            __nv_bfloat162 h01 = __nv_bfloat162(__float2bfloat16(v.x), __float2bfloat16(v.y));
            __nv_bfloat162 h23 = __nv_bfloat162(__float2bfloat16(v.z), __float2bfloat16(v.w));
            __nv_bfloat162 l01 = __nv_bfloat162(
                __float2bfloat16(v.x - __bfloat162float(h01.x)),
                __float2bfloat16(v.y - __bfloat162float(h01.y)));
            __nv_bfloat162 l23 = __nv_bfloat162(
                __float2bfloat16(v.z - __bfloat162float(h23.x)),
                __float2bfloat16(v.w - __bfloat162float(h23.y)));
            uint32_t o = (uint32_t)r * SA + (uint32_t)kq * 8;
            *(uint2*)(Ah + o) = make_uint2(*(uint32_t*)&h01, *(uint32_t*)&h23);
            *(uint2*)(Al + o) = make_uint2(*(uint32_t*)&l01, *(uint32_t*)&l23);
        }
        // ---- B: 128 rows(N) x 64 k bf16 hi/lo copy ----
#pragma unroll
        for (int i = 0; i < 4; i++) {
            int f = tid + i * 256;
            int r = f >> 3;                   // n row 0..127
            int g = f & 7;                    // 8-k group
            size_t si = (size_t)(colBase + r) * KTOT + ck * KC + g * 8;
            uint32_t o = (uint32_t)r * SA + (uint32_t)g * 16;
            *(uint4*)(Bh + o) = *(const uint4*)(Bhi + si);
            *(uint4*)(Bl + o) = *(const uint4*)(Blo + si);
        }
        __syncthreads();

        // ---- 3 split passes: (Ahi,Bhi), (Ahi,Blo), (Alo,Bhi) ----
#pragma unroll
        for (int pass = 0; pass < 3; pass++) {
            const uint32_t sa = (pass == 2) ? sAl : sAh;
            const uint32_t sb = (pass == 1) ? sBl : sBh;
#pragma unroll
            for (int ks = 0; ks < KC / 16; ks++) {
                const int k0 = ks * 16;
                uint32_t af[2][4];
#pragma unroll
                for (int mt = 0; mt < 2; mt++) {
                    int row = warpM * 32 + mt * 16 + (lane & 15);
                    uint32_t addr = sa + (uint32_t)row * SA +
                                    (uint32_t)(k0 + ((lane >> 4) << 3)) * 2;
                    LDSM_X4(af[mt], addr);
                }
                uint32_t bf[NT16][4];
#pragma unroll
                for (int nt = 0; nt < NT16; nt++) {
                    int nrow = warpN * WN + nt * 16 + ((lane >> 4) << 3) + (lane & 7);
                    uint32_t addr = sb + (uint32_t)nrow * SA +
                                    (uint32_t)(k0 + (((lane >> 3) & 1) << 3)) * 2;
                    LDSM_X4(bf[nt], addr);
                }
#pragma unroll
                for (int mt = 0; mt < 2; mt++)
#pragma unroll
                    for (int j = 0; j < N8; j++)
                        mma16816(acc[mt][j], af[mt],
                                 bf[j >> 1][(j & 1) * 2], bf[j >> 1][(j & 1) * 2 + 1]);
            }
        }
        __syncthreads();
    }

    // ---- epilogue ----
#pragma unroll
    for (int mt = 0; mt < 2; mt++) {
        int r0 = rowBase + warpM * 32 + mt * 16 + (lane >> 2);
#pragma unroll
        for (int j = 0; j < N8; j++) {
            int col = colBase + warpN * WN + j * 8 + (lane & 3) * 2;
            if (r0 < M)
                *(float2*)(C + (size_t)r0 * NTOT + col) = make_float2(acc[mt][j][0], acc[mt][j][1]);
            if (r0 + 8 < M)
                *(float2*)(C + (size_t)(r0 + 8) * NTOT + col) = make_float2(acc[mt][j][2], acc[mt][j][3]);
        }
    }
}

// ---------------- layer-1 gather + BN stats ----------------
__global__ __launch_bounds__(256) void k_gather_bn(const float* __restrict__ b1, int M, int E) {
    __shared__ float s_sum[HID_CH], s_sq[HID_CH];
    const int tid = threadIdx.x, lane = tid & 31, wid = tid >> 5;
    s_sum[tid] = 0.f; s_sq[tid] = 0.f;
    __syncthreads();

    const float4* b4 = (const float4*)b1;
    const float4 bb0 = b4[lane], bb1 = b4[lane + 32];
    float ls[8] = {0,0,0,0,0,0,0,0}, lq[8] = {0,0,0,0,0,0,0,0};

    for (int d = blockIdx.x * 8 + wid; d < M; d += gridDim.x * 8) {
        float disd = g_dis[d];
        int beg = g_off[d];
        int end = (d == M - 1) ? E : g_off[d + 1];
        float4 a0 = make_float4(0.f,0.f,0.f,0.f), a1 = make_float4(0.f,0.f,0.f,0.f);

        int j = beg;
        for (; j + 2 <= end; j += 2) {
            int s0 = g_esrc[j], s1 = g_esrc[j + 1];
            float w0 = disd * g_dis[s0];
            float w1 = disd * g_dis[s1];
            const float4* r0 = (const float4*)(g_h1 + (size_t)s0 * HID_CH);
            const float4* r1 = (const float4*)(g_h1 + (size_t)s1 * HID_CH);
            float4 v00 = r0[lane], v01 = r0[lane + 32];
            float4 v10 = r1[lane], v11 = r1[lane + 32];
            fma4(a0, v00, w0); fma4(a1, v01, w0);
            fma4(a0, v10, w1); fma4(a1, v11, w1);
        }
        if (j < end) {
            int s0 = g_esrc[j];
            float w0 = disd * g_dis[s0];
            const float4* r0 = (const float4*)(g_h1 + (size_t)s0 * HID_CH);
            float4 v00 = r0[lane], v01 = r0[lane + 32];
            fma4(a0, v00, w0); fma4(a1, v01, w0);
        }
        float self = disd * disd;
        const float4* hd = (const float4*)(g_h1 + (size_t)d * HID_CH);
        float4 sv0 = hd[lane], sv1 = hd[lane + 32];
        fma4(a0, sv0, self); fma4(a1, sv1, self);
        a0.x += bb0.x; a0.y += bb0.y; a0.z += bb0.z; a0.w += bb0.w;
        a1.x += bb1.x; a1.y += bb1.y; a1.z += bb1.z; a1.w += bb1.w;

        float4* yr = (float4*)(g_y1 + (size_t)d * HID_CH);
        yr[lane] = a0; yr[lane + 32] = a1;

        ls[0] += a0.x; lq[0] += a0.x * a0.x;
        ls[1] += a0.y; lq[1] += a0.y * a0.y;
        ls[2] += a0.z; lq[2] += a0.z * a0.z;
        ls[3] += a0.w; lq[3] += a0.w * a0.w;
        ls[4] += a1.x; lq[4] += a1.x * a1.x;
        ls[5] += a1.y; lq[5] += a1.y * a1.y;
        ls[6] += a1.z; lq[6] += a1.z * a1.z;
        ls[7] += a1.w; lq[7] += a1.w * a1.w;
    }

#pragma unroll
    for (int j = 0; j < 4; j++) {
        atomicAdd(&s_sum[4 * lane + j], ls[j]);
        atomicAdd(&s_sq [4 * lane + j], lq[j]);
        atomicAdd(&s_sum[128 + 4 * lane + j], ls[4 + j]);
        atomicAdd(&s_sq [128 + 4 * lane + j], lq[4 + j]);
    }
    __syncthreads();
    atomicAdd(&g_bnsum[tid], s_sum[tid]);
    atomicAdd(&g_bnsq[tid],  s_sq[tid]);
}

__global__ void k_bn_finalize(const float* __restrict__ gamma,
                              const float* __restrict__ beta, int M) {
    int c = threadIdx.x;
    if (c >= HID_CH) return;
    float inv = 1.0f / (float)M;
    float mu  = g_bnsum[c] * inv;
    float var = g_bnsq[c] * inv - mu * mu;
    float rs  = rsqrtf(var + BN_EPS);
    float sc  = gamma[c] * rs;
    g_scale[c] = sc;
    g_shift[c] = beta[c] - mu * sc;
}

// ---------------- layer-2 gather ----------------
__global__ __launch_bounds__(256) void k_gather_out(float* __restrict__ out,
                                                    const float* __restrict__ b2, int M, int E) {
    const int tid = threadIdx.x, lane = tid & 31, wid = tid >> 5;
    const float4 bb = ((const float4*)b2)[lane];

    for (int d = blockIdx.x * 8 + wid; d < M; d += gridDim.x * 8) {
        float disd = g_dis[d];
        int beg = g_off[d];
        int end = (d == M - 1) ? E : g_off[d + 1];
        float4 a = make_float4(0.f,0.f,0.f,0.f);

        int j = beg;
        for (; j + 2 <= end; j += 2) {
            int s0 = g_esrc[j], s1 = g_esrc[j + 1];
            float w0 = disd * g_dis[s0];
            float w1 = disd * g_dis[s1];
            float4 v0 = ((const float4*)(g_h2 + (size_t)s0 * OUT_CH))[lane];
            float4 v1 = ((const float4*)(g_h2 + (size_t)s1 * OUT_CH))[lane];
            fma4(a, v0, w0);
            fma4(a, v1, w1);
        }
        if (j < end) {
            int s0 = g_esrc[j];
            float w0 = disd * g_dis[s0];
            float4 v0 = ((const float4*)(g_h2 + (size_t)s0 * OUT_CH))[lane];
            fma4(a, v0, w0);
        }
        float self = disd * disd;
        float4 sv = ((const float4*)(g_h2 + (size_t)d * OUT_CH))[lane];
        fma4(a, sv, self);
        a.x += bb.x; a.y += bb.y; a.z += bb.z; a.w += bb.w;
        ((float4*)(out + (size_t)d * OUT_CH))[lane] = a;
    }
}

// ---------------- launch ----------------
extern "C" void kernel_launch(void* const* d_in, const int* in_sizes, int n_in,
                              void* d_out, int out_size) {
    const float* x      = (const float*)d_in[0];
    const int*   ei     = (const int*)  d_in[1];
    const float* W1     = (const float*)d_in[2];
    const float* b1     = (const float*)d_in[3];
    const float* gamma1 = (const float*)d_in[4];
    const float* beta1  = (const float*)d_in[5];
    const float* W2     = (const float*)d_in[6];
    const float* b2     = (const float*)d_in[7];
    float* out = (float*)d_out;

    const int M = in_sizes[0] / IN_CH;    // 50000
    const int E = in_sizes[1] / 2;        // 800000
    const int* src = ei;
    const int* dst = ei + E;

    float *ph1, *py1, *ph2;
    cudaGetSymbolAddress((void**)&ph1, g_h1);
    cudaGetSymbolAddress((void**)&py1, g_y1);
    cudaGetSymbolAddress((void**)&ph2, g_h2);
    __nv_bfloat16 *pw1h, *pw1l, *pw2h, *pw2l;
    cudaGetSymbolAddress((void**)&pw1h, g_wt1hi);
    cudaGetSymbolAddress((void**)&pw1l, g_wt1lo);
    cudaGetSymbolAddress((void**)&pw2h, g_wt2hi);
    cudaGetSymbolAddress((void**)&pw2l, g_wt2lo);

    const int SM1 = (128 + 128 + 128 + 128) * SA;  // BM=128: 73728 B
    const int SM2 = (64 + 64 + 128 + 128) * SA;    // BM=64:  55296 B
    cudaFuncSetAttribute(k_mma_gemm<false, IN_CH, HID_CH, 128>,
                         cudaFuncAttributeMaxDynamicSharedMemorySize, SM1);
    cudaFuncSetAttribute(k_mma_gemm<true, HID_CH, OUT_CH, 64>,
                         cudaFuncAttributeMaxDynamicSharedMemorySize, SM2);

    const int NB = (M + 255) / 256;

    // CSR build + normalization + weight prep
    k_init<<<256, 256>>>(M);
    k_prep_w<<<(2 * IN_CH * HID_CH + 255) / 256, 256>>>(W1, W2);
    k_deg<<<(E + 255) / 256, 256>>>(dst, E);
    k_dis<<<(M + 255) / 256, 256>>>(M);
    k_scan1<<<NB, 256>>>(M);
    k_scan2<<<1, 256>>>(NB);
    k_scan3<<<(M + 255) / 256, 256>>>(M);
    k_fill<<<(E + 255) / 256, 256>>>(src, dst, E);

    // layer 1: h1 = x @ W1 (mma.sync split-bf16), tiles 128x128
    {
        dim3 grid(HID_CH / 128, (M + 127) / 128);
        k_mma_gemm<false, IN_CH, HID_CH, 128><<<grid, 256, SM1>>>(x, pw1h, pw1l, ph1, M);
    }
    k_gather_bn<<<592, 256>>>(b1, M, E);
    k_bn_finalize<<<1, HID_CH>>>(gamma1, beta1, M);

    // layer 2: h2 = relu(bn(y1)) @ W2, tiles 64x128 (BN+ReLU fused into A convert)
    {
        dim3 grid(OUT_CH / 128, (M + 63) / 64);
        k_mma_gemm<true, HID_CH, OUT_CH, 64><<<grid, 256, SM2>>>(py1, pw2h, pw2l, ph2, M);
    }
    k_gather_out<<<592, 256>>>(out, b2, M, E);
}